// round 4
// baseline (speedup 1.0000x reference)
#include <cuda_runtime.h>

// Problem constants (fixed by the reference):
//   N=8192, M=128, DZ=128, DX=128, HEADS=4
//   out[n,m,h] = relu( sum_d z[n,d]*W[d,h] + sum_d x[d,m]*W[DZ+d,h] + b[h] )
// H=4 => out[n,m,:] is exactly one float4:
//   out4[n*M+m] = relu( zw4[n] + xwb4[m] )   (bias folded into xwb4)

#define N_ROWS   8192
#define M_COLS   128
#define D_Z      128
#define D_X      128
#define HEADS    4
#define NBLOCKS  256
#define NTHREADS 256
#define ROWS_PB  (N_ROWS / NBLOCKS)   // 32 rows per block

__global__ __launch_bounds__(NTHREADS)
void graph_aggr_mlp_kernel(const float* __restrict__ z,
                           const float* __restrict__ x,
                           const float* __restrict__ W,
                           const float* __restrict__ b,
                           float4* __restrict__ out4)
{
    __shared__ float4 sW[D_Z + D_X];   // W as 256 float4 rows (h fastest). 4KB
    __shared__ float4 sXWB[M_COLS];    // x^T@W2 + b, per m. 2KB
    __shared__ float4 sZW[ROWS_PB];    // z@W1 for this block's rows. 512B

    const int tid  = threadIdx.x;
    const int bid  = blockIdx.x;
    const int lane = tid & 31;
    const int warp = tid >> 5;
    const int n0   = bid * ROWS_PB;

    // Load full W (256 float4 = 1024 floats) into shared, one float4/thread.
    sW[tid] = reinterpret_cast<const float4*>(W)[tid];
    __syncthreads();

    if (tid < 128) {
        // Warps 0-3: xwb4[m] = b + sum_d x[d,m] * W[DZ+d,:]
        const int m = tid;
        float4 acc = *reinterpret_cast<const float4*>(b);
        #pragma unroll 8
        for (int d = 0; d < D_X; ++d) {
            const float xv = x[d * M_COLS + m];          // coalesced across m
            const float4 w = sW[D_Z + d];                // uniform broadcast
            acc.x = fmaf(xv, w.x, acc.x);
            acc.y = fmaf(xv, w.y, acc.y);
            acc.z = fmaf(xv, w.z, acc.z);
            acc.w = fmaf(xv, w.w, acc.w);
        }
        sXWB[m] = acc;
    } else {
        // Warps 4-7: zw4 for 32 rows, 8 rows per warp, warp-per-row reduce.
        const int w8 = warp - 4;                         // 0..3
        for (int k = 0; k < 8; ++k) {
            const int nl = w8 * 8 + k;
            const float* zr = z + (size_t)(n0 + nl) * D_Z;
            float4 acc = make_float4(0.f, 0.f, 0.f, 0.f);
            #pragma unroll
            for (int j = 0; j < 4; ++j) {
                const int d = lane + 32 * j;
                const float zv = zr[d];                  // 128B coalesced
                const float4 w = sW[d];
                acc.x = fmaf(zv, w.x, acc.x);
                acc.y = fmaf(zv, w.y, acc.y);
                acc.z = fmaf(zv, w.z, acc.z);
                acc.w = fmaf(zv, w.w, acc.w);
            }
            #pragma unroll
            for (int off = 16; off; off >>= 1) {
                acc.x += __shfl_xor_sync(0xffffffffu, acc.x, off);
                acc.y += __shfl_xor_sync(0xffffffffu, acc.y, off);
                acc.z += __shfl_xor_sync(0xffffffffu, acc.z, off);
                acc.w += __shfl_xor_sync(0xffffffffu, acc.w, off);
            }
            if (lane == 0) sZW[nl] = acc;
        }
    }
    __syncthreads();

    // Stream output: 32 rows * 128 m = 4096 float4 per block, 16 per thread.
    const size_t base = (size_t)n0 * M_COLS;
    #pragma unroll
    for (int it = 0; it < 16; ++it) {
        const int i  = it * NTHREADS + tid;   // 0..4095
        const int nl = i >> 7;                // local row (broadcast per warp)
        const int m  = i & 127;               // conflict-free LDS.128
        const float4 a = sZW[nl];
        const float4 c = sXWB[m];
        float4 r;
        r.x = fmaxf(a.x + c.x, 0.f);
        r.y = fmaxf(a.y + c.y, 0.f);
        r.z = fmaxf(a.z + c.z, 0.f);
        r.w = fmaxf(a.w + c.w, 0.f);
        out4[base + i] = r;                   // fully coalesced 16B stores
    }
}

extern "C" void kernel_launch(void* const* d_in, const int* in_sizes, int n_in,
                              void* d_out, int out_size)
{
    const float* z = (const float*)d_in[0];   // [8192,128]
    const float* x = (const float*)d_in[1];   // [128,128]
    const float* W = (const float*)d_in[2];   // [256,4]
    const float* b = (const float*)d_in[3];   // [4]
    float4* out4   = (float4*)d_out;          // [8192,128,4] fp32 viewed as float4

    graph_aggr_mlp_kernel<<<NBLOCKS, NTHREADS>>>(z, x, W, b, out4);
}

// round 5
// speedup vs baseline: 1.1346x; 1.1346x over previous
#include <cuda_runtime.h>

// out[n,m,:4] = relu( zw4[n] + xwb4[m] ),  zw4 = z@W1, xwb4 = x^T@W2 + b
// N=8192, M=128, DZ=DX=128, H=4.
// Two-phase: (A) tiny precompute of zw4/xwb4 into device scratch,
//            (B) full-occupancy broadcast-add stream of 1M float4.

#define N_ROWS   8192
#define M_COLS   128
#define D_Z      128
#define D_X      128

__device__ float4 g_zw[N_ROWS];    // 128 KB scratch (allowed: __device__ global)
__device__ float4 g_xwb[M_COLS];   // 2 KB

// ---------------- Kernel A: precompute ----------------
// grid = 257 blocks x 256 threads.
// blocks 0..255 : zw4 for 32 rows each (8 warps x 4 rows, ILP across rows)
// block  256    : xwb4[m] = b + sum_d x[d,m] * W2[d,:]
__global__ __launch_bounds__(256)
void precompute_kernel(const float* __restrict__ z,
                       const float* __restrict__ x,
                       const float* __restrict__ W,
                       const float* __restrict__ b)
{
    __shared__ float4 sW[D_Z + D_X];           // 256 float4 (h fastest), 4KB
    const int tid  = threadIdx.x;
    const int bid  = blockIdx.x;
    const int lane = tid & 31;
    const int warp = tid >> 5;

    sW[tid] = reinterpret_cast<const float4*>(W)[tid];
    __syncthreads();

    if (bid == 256) {
        // xwb: one thread per m
        if (tid < M_COLS) {
            const int m = tid;
            float4 acc = *reinterpret_cast<const float4*>(b);
            #pragma unroll 8
            for (int d = 0; d < D_X; ++d) {
                const float xv = x[d * M_COLS + m];      // coalesced across m
                const float4 w = sW[D_Z + d];            // broadcast
                acc.x = fmaf(xv, w.x, acc.x);
                acc.y = fmaf(xv, w.y, acc.y);
                acc.z = fmaf(xv, w.z, acc.z);
                acc.w = fmaf(xv, w.w, acc.w);
            }
            g_xwb[m] = acc;
        }
        return;
    }

    // zw: this block owns rows [bid*32, bid*32+32); each warp does 4 rows
    const int n0 = bid * 32 + warp * 4;

    // Lane covers d = lane*4 .. lane*4+3; W rows for those d, loaded once.
    const float4 w0 = sW[lane * 4 + 0];
    const float4 w1 = sW[lane * 4 + 1];
    const float4 w2 = sW[lane * 4 + 2];
    const float4 w3 = sW[lane * 4 + 3];

    float4 acc[4];
    #pragma unroll
    for (int r = 0; r < 4; ++r) {
        const float4 zv = reinterpret_cast<const float4*>(
                              z + (size_t)(n0 + r) * D_Z)[lane];  // coalesced 512B
        float4 a;
        a.x = zv.x * w0.x; a.y = zv.x * w0.y; a.z = zv.x * w0.z; a.w = zv.x * w0.w;
        a.x = fmaf(zv.y, w1.x, a.x); a.y = fmaf(zv.y, w1.y, a.y);
        a.z = fmaf(zv.y, w1.z, a.z); a.w = fmaf(zv.y, w1.w, a.w);
        a.x = fmaf(zv.z, w2.x, a.x); a.y = fmaf(zv.z, w2.y, a.y);
        a.z = fmaf(zv.z, w2.z, a.z); a.w = fmaf(zv.z, w2.w, a.w);
        a.x = fmaf(zv.w, w3.x, a.x); a.y = fmaf(zv.w, w3.y, a.y);
        a.z = fmaf(zv.w, w3.z, a.z); a.w = fmaf(zv.w, w3.w, a.w);
        acc[r] = a;
    }

    // Butterfly reduce all 4 rows together (16 independent chains -> ILP hides
    // the 26-cycle SHFL latency instead of serializing per row).
    #pragma unroll
    for (int off = 16; off; off >>= 1) {
        #pragma unroll
        for (int r = 0; r < 4; ++r) {
            acc[r].x += __shfl_xor_sync(0xffffffffu, acc[r].x, off);
            acc[r].y += __shfl_xor_sync(0xffffffffu, acc[r].y, off);
            acc[r].z += __shfl_xor_sync(0xffffffffu, acc[r].z, off);
            acc[r].w += __shfl_xor_sync(0xffffffffu, acc[r].w, off);
        }
    }
    if (lane < 4) g_zw[n0 + lane] = acc[lane];
}

// ---------------- Kernel B: pure broadcast-add stream ----------------
// grid = 1024 blocks x 256 threads: one warp per n-row.
// Per lane: 1 uniform LDG (zw), 4 L1-hit LDGs (xwb), 4 coalesced STG.128.
__global__ __launch_bounds__(256)
void stream_kernel(float4* __restrict__ out4)
{
    const int lane = threadIdx.x & 31;
    const int row  = (blockIdx.x << 3) + (threadIdx.x >> 5);  // global warp id
    const float4 a = g_zw[row];                                // warp-uniform
    float4* __restrict__ orow = out4 + (size_t)row * M_COLS;

    #pragma unroll
    for (int j = 0; j < 4; ++j) {
        const int m = lane + (j << 5);
        const float4 c = g_xwb[m];     // 2KB, L1-resident
        float4 r;
        r.x = fmaxf(a.x + c.x, 0.f);
        r.y = fmaxf(a.y + c.y, 0.f);
        r.z = fmaxf(a.z + c.z, 0.f);
        r.w = fmaxf(a.w + c.w, 0.f);
        orow[m] = r;                   // coalesced STG.128
    }
}

extern "C" void kernel_launch(void* const* d_in, const int* in_sizes, int n_in,
                              void* d_out, int out_size)
{
    const float* z = (const float*)d_in[0];   // [8192,128]
    const float* x = (const float*)d_in[1];   // [128,128]
    const float* W = (const float*)d_in[2];   // [256,4]
    const float* b = (const float*)d_in[3];   // [4]
    float4* out4   = (float4*)d_out;

    precompute_kernel<<<257, 256>>>(z, x, W, b);
    stream_kernel<<<1024, 256>>>(out4);       // same stream: ordered after A
}

// round 6
// speedup vs baseline: 1.4048x; 1.2381x over previous
#include <cuda_runtime.h>

// out[n,m,:4] = relu( zw4[n] + xwb4[m] ),  zw4 = z@W1, xwb4 = x^T@W2 + b
// N=8192, M=128, DZ=DX=128, H=4.

#define N_ROWS   8192
#define M_COLS   128
#define D_Z      128
#define D_X      128

__device__ float4 g_zw[N_ROWS];    // 128 KB scratch
__device__ float4 g_xwb[M_COLS];   // 2 KB

// ---------------- Kernel A: precompute ----------------
// blocks 0..255 : zw4 for 32 rows each (8 warps x 4 rows, ILP across rows)
// block  256    : xwb4, d-reduction parallelized across 8 warps
__global__ __launch_bounds__(256)
void precompute_kernel(const float* __restrict__ z,
                       const float* __restrict__ x,
                       const float* __restrict__ W,
                       const float* __restrict__ b)
{
    __shared__ float4 sW[D_Z + D_X];           // 256 float4 (h fastest), 4KB
    const int tid  = threadIdx.x;
    const int bid  = blockIdx.x;
    const int lane = tid & 31;
    const int warp = tid >> 5;

    sW[tid] = reinterpret_cast<const float4*>(W)[tid];

    if (bid == 256) {
        // xwb[m] = b + sum_d x[d,m] * W2[d,:].  Warp w owns d in [16w,16w+16);
        // lane covers m = 4*lane .. 4*lane+3 via float4 loads of x rows.
        __shared__ float4 sPart[8][M_COLS];    // per-warp partials, 16KB
        __syncthreads();                       // sW ready

        const float4* x4 = reinterpret_cast<const float4*>(x);
        float4 acc[4] = {{0,0,0,0},{0,0,0,0},{0,0,0,0},{0,0,0,0}};
        const int d0 = warp * 16;
        #pragma unroll
        for (int i = 0; i < 16; ++i) {
            const int d = d0 + i;
            const float4 xv = x4[d * 32 + lane];   // x[d, 4l..4l+3], coalesced
            const float4 w  = sW[D_Z + d];         // broadcast
            acc[0].x = fmaf(xv.x, w.x, acc[0].x); acc[0].y = fmaf(xv.x, w.y, acc[0].y);
            acc[0].z = fmaf(xv.x, w.z, acc[0].z); acc[0].w = fmaf(xv.x, w.w, acc[0].w);
            acc[1].x = fmaf(xv.y, w.x, acc[1].x); acc[1].y = fmaf(xv.y, w.y, acc[1].y);
            acc[1].z = fmaf(xv.y, w.z, acc[1].z); acc[1].w = fmaf(xv.y, w.w, acc[1].w);
            acc[2].x = fmaf(xv.z, w.x, acc[2].x); acc[2].y = fmaf(xv.z, w.y, acc[2].y);
            acc[2].z = fmaf(xv.z, w.z, acc[2].z); acc[2].w = fmaf(xv.z, w.w, acc[2].w);
            acc[3].x = fmaf(xv.w, w.x, acc[3].x); acc[3].y = fmaf(xv.w, w.y, acc[3].y);
            acc[3].z = fmaf(xv.w, w.z, acc[3].z); acc[3].w = fmaf(xv.w, w.w, acc[3].w);
        }
        #pragma unroll
        for (int c = 0; c < 4; ++c) sPart[warp][lane * 4 + c] = acc[c];
        __syncthreads();

        if (tid < M_COLS) {
            float4 s = *reinterpret_cast<const float4*>(b);
            #pragma unroll
            for (int w = 0; w < 8; ++w) {
                const float4 p = sPart[w][tid];
                s.x += p.x; s.y += p.y; s.z += p.z; s.w += p.w;
            }
            g_xwb[tid] = s;
        }
        return;
    }

    __syncthreads();                           // sW ready

    // zw: block owns rows [bid*32, bid*32+32); each warp does 4 rows with ILP.
    const int n0 = bid * 32 + warp * 4;
    const float4 w0 = sW[lane * 4 + 0];
    const float4 w1 = sW[lane * 4 + 1];
    const float4 w2 = sW[lane * 4 + 2];
    const float4 w3 = sW[lane * 4 + 3];

    float4 acc[4];
    #pragma unroll
    for (int r = 0; r < 4; ++r) {
        const float4 zv = reinterpret_cast<const float4*>(
                              z + (size_t)(n0 + r) * D_Z)[lane];  // coalesced 512B
        float4 a;
        a.x = zv.x * w0.x; a.y = zv.x * w0.y; a.z = zv.x * w0.z; a.w = zv.x * w0.w;
        a.x = fmaf(zv.y, w1.x, a.x); a.y = fmaf(zv.y, w1.y, a.y);
        a.z = fmaf(zv.y, w1.z, a.z); a.w = fmaf(zv.y, w1.w, a.w);
        a.x = fmaf(zv.z, w2.x, a.x); a.y = fmaf(zv.z, w2.y, a.y);
        a.z = fmaf(zv.z, w2.z, a.z); a.w = fmaf(zv.z, w2.w, a.w);
        a.x = fmaf(zv.w, w3.x, a.x); a.y = fmaf(zv.w, w3.y, a.y);
        a.z = fmaf(zv.w, w3.z, a.z); a.w = fmaf(zv.w, w3.w, a.w);
        acc[r] = a;
    }
    #pragma unroll
    for (int off = 16; off; off >>= 1) {       // 16 independent chains -> ILP
        #pragma unroll
        for (int r = 0; r < 4; ++r) {
            acc[r].x += __shfl_xor_sync(0xffffffffu, acc[r].x, off);
            acc[r].y += __shfl_xor_sync(0xffffffffu, acc[r].y, off);
            acc[r].z += __shfl_xor_sync(0xffffffffu, acc[r].z, off);
            acc[r].w += __shfl_xor_sync(0xffffffffu, acc[r].w, off);
        }
    }
    if (lane < 4) g_zw[n0 + lane] = acc[lane];
}

// ---------------- Kernel B: broadcast-add stream, 4 rows per warp ----------------
// grid = 256 blocks x 256 threads = 2048 warps; warp owns rows [4w, 4w+4).
// Front-batched: 4 uniform zw LDGs + 4 xwb LDGs (MLP=8), then 16 STG.128/lane.
__global__ __launch_bounds__(256)
void stream_kernel(float4* __restrict__ out4)
{
    const int lane = threadIdx.x & 31;
    const int gw   = (blockIdx.x << 3) + (threadIdx.x >> 5);   // 0..2047
    const int r0   = gw << 2;

    const float4 a0 = g_zw[r0 + 0];            // warp-uniform loads
    const float4 a1 = g_zw[r0 + 1];
    const float4 a2 = g_zw[r0 + 2];
    const float4 a3 = g_zw[r0 + 3];
    const float4 c0 = g_xwb[lane];
    const float4 c1 = g_xwb[lane + 32];
    const float4 c2 = g_xwb[lane + 64];
    const float4 c3 = g_xwb[lane + 96];

    float4* __restrict__ o = out4 + ((size_t)r0 << 7);   // r0 * 128

    #define EMIT(AR, J, CV, MOFF)                                   \
    {                                                               \
        float4 r;                                                   \
        r.x = fmaxf(AR.x + CV.x, 0.f);                              \
        r.y = fmaxf(AR.y + CV.y, 0.f);                              \
        r.z = fmaxf(AR.z + CV.z, 0.f);                              \
        r.w = fmaxf(AR.w + CV.w, 0.f);                              \
        o[(J << 7) + MOFF + lane] = r;                              \
    }

    EMIT(a0, 0, c0,  0) EMIT(a0, 0, c1, 32) EMIT(a0, 0, c2, 64) EMIT(a0, 0, c3, 96)
    EMIT(a1, 1, c0,  0) EMIT(a1, 1, c1, 32) EMIT(a1, 1, c2, 64) EMIT(a1, 1, c3, 96)
    EMIT(a2, 2, c0,  0) EMIT(a2, 2, c1, 32) EMIT(a2, 2, c2, 64) EMIT(a2, 2, c3, 96)
    EMIT(a3, 3, c0,  0) EMIT(a3, 3, c1, 32) EMIT(a3, 3, c2, 64) EMIT(a3, 3, c3, 96)
    #undef EMIT
}

extern "C" void kernel_launch(void* const* d_in, const int* in_sizes, int n_in,
                              void* d_out, int out_size)
{
    const float* z = (const float*)d_in[0];   // [8192,128]
    const float* x = (const float*)d_in[1];   // [128,128]
    const float* W = (const float*)d_in[2];   // [256,4]
    const float* b = (const float*)d_in[3];   // [4]
    float4* out4   = (float4*)d_out;

    precompute_kernel<<<257, 256>>>(z, x, W, b);
    stream_kernel<<<256, 256>>>(out4);
}